// round 7
// baseline (speedup 1.0000x reference)
#include <cuda_runtime.h>
#include <cstdint>

#define N      2048
#define DIN    256
#define PROJC  256
#define PTM    8           // proj kernel row tile
#define TM     8           // attn rows per CTA
#define NW     8           // warps per attn CTA
#define STAGES 4
#define NIT    (N / NW)    // 256 iterations, j = w + 8k

// 2 MB scratch for projection output: cols = [Q(64) | K(64) | V(64) | R(64)]
__device__ float g_proj[N * PROJC];

// ---------------------------------------------------------------------------
// Kernel 1: proj = H @ W^T
// ---------------------------------------------------------------------------
__global__ __launch_bounds__(256) void proj_kernel(const float* __restrict__ H,
                                                   const float* __restrict__ W,
                                                   float* __restrict__ proj) {
    __shared__ float Hsh[PTM][64];
    extern __shared__ float Wsh[];          // [256][65]
    const int t  = threadIdx.x;
    const int i0 = blockIdx.x * PTM;

    float acc[PTM];
#pragma unroll
    for (int i = 0; i < PTM; i++) acc[i] = 0.f;

    for (int kc = 0; kc < DIN; kc += 64) {
        if (t < PTM * 64 / 4) {
#pragma unroll
            for (int r = 0; r < 4; r++) {
                int idx = t + r * 128;
                if (idx < PTM * 64)
                    Hsh[idx >> 6][idx & 63] = H[(i0 + (idx >> 6)) * DIN + kc + (idx & 63)];
            }
        }
#pragma unroll 8
        for (int r = 0; r < 64; r++) {
            int idx = t + r * 256;
            Wsh[(idx >> 6) * 65 + (idx & 63)] = W[(idx >> 6) * DIN + kc + (idx & 63)];
        }
        __syncthreads();
#pragma unroll
        for (int k = 0; k < 64; k++) {
            float w = Wsh[t * 65 + k];
#pragma unroll
            for (int i = 0; i < PTM; i++) acc[i] = fmaf(Hsh[i][k], w, acc[i]);
        }
        __syncthreads();
    }
#pragma unroll
    for (int i = 0; i < PTM; i++) proj[(i0 + i) * PROJC + t] = acc[i];
}

// ---------------------------------------------------------------------------
__device__ __forceinline__ float combine2(float a, float b, int mask, int l) {
    float sel = (l & mask) ? a : b;
    float t = __shfl_xor_sync(0xffffffffu, sel, mask);
    return (l & mask) ? (b + t) : (a + t);
}

__device__ __forceinline__ void cp16(uint32_t s, const void* g) {
    asm volatile("cp.async.cg.shared.global [%0], [%1], 16;\n" :: "r"(s), "l"(g));
}

__device__ __forceinline__ float ex2f(float x) {
    float y;
    asm("ex2.approx.ftz.f32 %0, %1;" : "=f"(y) : "f"(x));
    return y;
}

// ---------------------------------------------------------------------------
// Kernel 2: fused scores + max-free online softmax (base-2) + P@V.
// 8 warps / 256 threads, 2 CTAs/SM -> whole grid resident in one wave.
// Warp w streams D[i0..i0+7, j=w+8k, :] through a private 4-stage ring.
// Lane l owns dims {2l, 2l+1}. Tree results broadcast via shfl.idx (no smem
// scratch, no __syncwarp in the loop). Cross-warp combine in a short epilogue.
// ---------------------------------------------------------------------------
__global__ __launch_bounds__(256, 2) void attn_kernel(const float* __restrict__ D,
                                                      const float* __restrict__ proj,
                                                      float* __restrict__ out) {
    extern __shared__ float smem[];
    const int t  = threadIdx.x;
    const int w  = t >> 5;
    const int l  = t & 31;
    const int i0 = blockIdx.x * TM;

    float* wbuf = smem + w * (STAGES * 512);               // 4 stages x 2KB
    const uint32_t wbuf_s = (uint32_t)__cvta_generic_to_shared(wbuf);

    // scale * log2(e): softmax in base 2 (ex2 of pre-scaled scores).
    const float SCL = 0.08838834764831845f * 1.4426950408889634f;

    // Pre-scaled Q,R fragments for the tile's 8 rows (dims 2l,2l+1).
    float2 q2[TM], r2[TM];
#pragma unroll
    for (int i = 0; i < TM; i++) {
        const float* row = proj + (size_t)(i0 + i) * PROJC;
        float2 qq = *(const float2*)(row + 2 * l);
        float2 rr = *(const float2*)(row + 192 + 2 * l);
        q2[i] = make_float2(qq.x * SCL, qq.y * SCL);
        r2[i] = make_float2(rr.x * SCL, rr.y * SCL);
    }

    // Prologue: fill all 4 stages. Stage = 8 rows x 256B; lane l copies
    // 4 x 16B chunks: flat idx = l + 32c -> row = idx>>4, u = idx&15.
#pragma unroll
    for (int s = 0; s < STAGES; s++) {
        int j = w + NW * s;
#pragma unroll
        for (int c = 0; c < 4; c++) {
            int idx = l + 32 * c;
            const float* g = D + (((size_t)(i0 + (idx >> 4)) * N + j) << 6) + ((idx & 15) << 2);
            cp16(wbuf_s + (uint32_t)(s * 2048 + idx * 16), g);
        }
        asm volatile("cp.async.commit_group;\n" ::: "memory");
    }

    // Prefetch K/V for j = w.
    float2 kv = *(const float2*)(proj + (size_t)w * PROJC + 64 + 2 * l);
    float2 vv = *(const float2*)(proj + (size_t)w * PROJC + 128 + 2 * l);

    float  sum[TM];
    float2 acc[TM];
#pragma unroll
    for (int i = 0; i < TM; i++) { sum[i] = 0.f; acc[i] = make_float2(0.f, 0.f); }

#pragma unroll 4
    for (int k = 0; k < NIT; k++) {
        asm volatile("cp.async.wait_group 3;\n" ::: "memory");

        const float* Db = wbuf + (k & 3) * 512;
        float v[TM];
#pragma unroll
        for (int r = 0; r < TM; r++) {
            float2 dv = *(const float2*)(Db + r * 64 + 2 * l);
            v[r] = fmaf(dv.x, r2[r].x,
                   fmaf(dv.y, r2[r].y,
                   fmaf(kv.x, q2[r].x, kv.y * q2[r].y)));
        }
        // 8 simultaneous 32-lane reductions in 9 shfls (packed tree).
        float c0 = combine2(v[0], v[1], 16, l);
        float c1 = combine2(v[2], v[3], 16, l);
        float c2 = combine2(v[4], v[5], 16, l);
        float c3 = combine2(v[6], v[7], 16, l);
        float d0 = combine2(c0, c1, 8, l);
        float d1 = combine2(c2, c3, 8, l);
        float e0 = combine2(d0, d1, 4, l);
        float f  = e0 + __shfl_xor_sync(0xffffffffu, e0, 2);
        float g  = f + __shfl_xor_sync(0xffffffffu, f, 1);
        // Row r's sum lives on lanes 4*bitrev3(r)..+3; broadcast all 8.
        float s0 = __shfl_sync(0xffffffffu, g, 0);
        float s1 = __shfl_sync(0xffffffffu, g, 16);
        float s2 = __shfl_sync(0xffffffffu, g, 8);
        float s3 = __shfl_sync(0xffffffffu, g, 24);
        float s4 = __shfl_sync(0xffffffffu, g, 4);
        float s5 = __shfl_sync(0xffffffffu, g, 20);
        float s6 = __shfl_sync(0xffffffffu, g, 12);
        float s7 = __shfl_sync(0xffffffffu, g, 28);

        // Refill the stage we just consumed (j = w + 8*(k+4)).
        if (k + STAGES < NIT) {
            int j = w + NW * (k + STAGES);
#pragma unroll
            for (int c = 0; c < 4; c++) {
                int idx = l + 32 * c;
                const float* gp = D + (((size_t)(i0 + (idx >> 4)) * N + j) << 6) + ((idx & 15) << 2);
                cp16(wbuf_s + (uint32_t)((k & 3) * 2048 + idx * 16), gp);
            }
        }
        asm volatile("cp.async.commit_group;\n" ::: "memory");

        // Prefetch next K/V.
        int jn = (w + NW * (k + 1)) & (N - 1);
        float2 kn = *(const float2*)(proj + (size_t)jn * PROJC + 64 + 2 * l);
        float2 vn = *(const float2*)(proj + (size_t)jn * PROJC + 128 + 2 * l);

        float p;
        p = ex2f(s0); sum[0] += p; acc[0].x = fmaf(p, vv.x, acc[0].x); acc[0].y = fmaf(p, vv.y, acc[0].y);
        p = ex2f(s1); sum[1] += p; acc[1].x = fmaf(p, vv.x, acc[1].x); acc[1].y = fmaf(p, vv.y, acc[1].y);
        p = ex2f(s2); sum[2] += p; acc[2].x = fmaf(p, vv.x, acc[2].x); acc[2].y = fmaf(p, vv.y, acc[2].y);
        p = ex2f(s3); sum[3] += p; acc[3].x = fmaf(p, vv.x, acc[3].x); acc[3].y = fmaf(p, vv.y, acc[3].y);
        p = ex2f(s4); sum[4] += p; acc[4].x = fmaf(p, vv.x, acc[4].x); acc[4].y = fmaf(p, vv.y, acc[4].y);
        p = ex2f(s5); sum[5] += p; acc[5].x = fmaf(p, vv.x, acc[5].x); acc[5].y = fmaf(p, vv.y, acc[5].y);
        p = ex2f(s6); sum[6] += p; acc[6].x = fmaf(p, vv.x, acc[6].x); acc[6].y = fmaf(p, vv.y, acc[6].y);
        p = ex2f(s7); sum[7] += p; acc[7].x = fmaf(p, vv.x, acc[7].x); acc[7].y = fmaf(p, vv.y, acc[7].y);

        kv = kn; vv = vn;
    }

    asm volatile("cp.async.wait_group 0;\n" ::: "memory");

    // ---------------- epilogue: combine the 8 warps' partials ----------------
    __syncthreads();
    float* accsh = smem;                   // [8][8][64]
    float* sumsh = smem + NW * TM * 64;    // [8][8]
#pragma unroll
    for (int r = 0; r < TM; r++)
        *(float2*)(accsh + ((w * TM + r) * 64) + 2 * l) = acc[r];
    if (l == 0) {
#pragma unroll
        for (int r = 0; r < TM; r++) sumsh[w * TM + r] = sum[r];
    }
    __syncthreads();
    {
        float2 tot = make_float2(0.f, 0.f);
        float  st  = 0.f;
#pragma unroll
        for (int ww = 0; ww < NW; ww++) {
            float2 a = *(const float2*)(accsh + ((ww * TM + w) * 64) + 2 * l);
            tot.x += a.x; tot.y += a.y;
            st += sumsh[ww * TM + w];
        }
        float inv = 1.0f / st;
        *(float2*)(out + (size_t)(i0 + w) * 64 + 2 * l) = make_float2(tot.x * inv, tot.y * inv);
    }
}

// ---------------------------------------------------------------------------
extern "C" void kernel_launch(void* const* d_in, const int* in_sizes, int n_in,
                              void* d_out, int out_size) {
    const float* H = (const float*)d_in[0];
    const float* D = (const float*)d_in[1];
    const float* W = (const float*)d_in[2];
    float* out = (float*)d_out;

    const int proj_smem = 256 * 65 * 4;                               // 66,560 B
    const int attn_smem = (NW * STAGES * 512 + NW * TM) * 4;          // 65,792 B
    cudaFuncSetAttribute(proj_kernel, cudaFuncAttributeMaxDynamicSharedMemorySize, proj_smem);
    cudaFuncSetAttribute(attn_kernel, cudaFuncAttributeMaxDynamicSharedMemorySize, attn_smem);

    void* proj_ptr = nullptr;
    cudaGetSymbolAddress(&proj_ptr, g_proj);
    float* proj = (float*)proj_ptr;

    proj_kernel<<<N / PTM, 256, proj_smem>>>(H, W, proj);
    attn_kernel<<<N / TM, 256, attn_smem>>>(D, proj, out);
}

// round 8
// speedup vs baseline: 1.4108x; 1.4108x over previous
#include <cuda_runtime.h>
#include <cstdint>

#define N      2048
#define DIN    256
#define PROJC  256
#define TM     8           // attn rows per CTA
#define NW     8           // warps per attn CTA
#define STAGES 4
#define NIT    (N / NW)    // 256 iterations, j = w + 8k

// proj GEMM tiles
#define BM 64
#define BN 64
#define BK 32

// 2 MB scratch for projection output: cols = [Q(64) | K(64) | V(64) | R(64)]
__device__ float g_proj[N * PROJC];

// ---------------------------------------------------------------------------
// Kernel 1: proj = H @ W^T  — tiled GEMM, 64x64 tile, 4x4 micro-tile/thread.
// ---------------------------------------------------------------------------
__global__ __launch_bounds__(256) void proj_kernel(const float* __restrict__ H,
                                                   const float* __restrict__ W,
                                                   float* __restrict__ proj) {
    __shared__ float Hs[BK][BM + 4];    // transposed: Hs[k][m], 68-float rows (16B-aligned)
    __shared__ float Ws[BK][BN + 4];    // transposed: Ws[k][n]

    const int t  = threadIdx.x;
    const int tx = t & 15;
    const int ty = t >> 4;
    const int m0 = blockIdx.x * BM;
    const int n0 = blockIdx.y * BN;

    float acc[4][4];
#pragma unroll
    for (int i = 0; i < 4; i++)
#pragma unroll
        for (int j = 0; j < 4; j++) acc[i][j] = 0.f;

    for (int kc = 0; kc < DIN; kc += BK) {
        // Load 64x32 H tile and 64x32 W tile, both transposed into smem.
        // 512 float4 each; every thread moves 2.
#pragma unroll
        for (int q = 0; q < 2; q++) {
            int idx = t + q * 256;            // 0..511
            int row = idx >> 3;               // 0..63
            int k4  = idx & 7;                // float4 index along k
            float4 hv = *(const float4*)(H + (size_t)(m0 + row) * DIN + kc + k4 * 4);
            Hs[k4 * 4 + 0][row] = hv.x;
            Hs[k4 * 4 + 1][row] = hv.y;
            Hs[k4 * 4 + 2][row] = hv.z;
            Hs[k4 * 4 + 3][row] = hv.w;
            float4 wv = *(const float4*)(W + (size_t)(n0 + row) * DIN + kc + k4 * 4);
            Ws[k4 * 4 + 0][row] = wv.x;
            Ws[k4 * 4 + 1][row] = wv.y;
            Ws[k4 * 4 + 2][row] = wv.z;
            Ws[k4 * 4 + 3][row] = wv.w;
        }
        __syncthreads();
#pragma unroll
        for (int k = 0; k < BK; k++) {
            float4 a = *(const float4*)&Hs[k][ty * 4];
            float4 b = *(const float4*)&Ws[k][tx * 4];
            acc[0][0] = fmaf(a.x, b.x, acc[0][0]); acc[0][1] = fmaf(a.x, b.y, acc[0][1]);
            acc[0][2] = fmaf(a.x, b.z, acc[0][2]); acc[0][3] = fmaf(a.x, b.w, acc[0][3]);
            acc[1][0] = fmaf(a.y, b.x, acc[1][0]); acc[1][1] = fmaf(a.y, b.y, acc[1][1]);
            acc[1][2] = fmaf(a.y, b.z, acc[1][2]); acc[1][3] = fmaf(a.y, b.w, acc[1][3]);
            acc[2][0] = fmaf(a.z, b.x, acc[2][0]); acc[2][1] = fmaf(a.z, b.y, acc[2][1]);
            acc[2][2] = fmaf(a.z, b.z, acc[2][2]); acc[2][3] = fmaf(a.z, b.w, acc[2][3]);
            acc[3][0] = fmaf(a.w, b.x, acc[3][0]); acc[3][1] = fmaf(a.w, b.y, acc[3][1]);
            acc[3][2] = fmaf(a.w, b.z, acc[3][2]); acc[3][3] = fmaf(a.w, b.w, acc[3][3]);
        }
        __syncthreads();
    }
#pragma unroll
    for (int i = 0; i < 4; i++) {
        float4 o = make_float4(acc[i][0], acc[i][1], acc[i][2], acc[i][3]);
        *(float4*)(proj + (size_t)(m0 + ty * 4 + i) * PROJC + n0 + tx * 4) = o;
    }
}

// ---------------------------------------------------------------------------
__device__ __forceinline__ float combine2(float a, float b, int mask, int l) {
    float sel = (l & mask) ? a : b;
    float t = __shfl_xor_sync(0xffffffffu, sel, mask);
    return (l & mask) ? (b + t) : (a + t);
}

__device__ __forceinline__ void cp16(uint32_t s, const void* g) {
    asm volatile("cp.async.cg.shared.global [%0], [%1], 16;\n" :: "r"(s), "l"(g));
}

// ---------------------------------------------------------------------------
// Kernel 2: fused scores + max-free online softmax + P@V.  (exact R4 body)
// 8 warps / 256 threads, 2 CTAs/SM -> whole grid resident in one wave.
// Warp w streams D[i0..i0+7, j=w+8k, :] through a private 4-stage ring.
// Lane l owns dims {2l, 2l+1}. Cross-warp combine in a short epilogue.
// ---------------------------------------------------------------------------
__global__ __launch_bounds__(256, 2) void attn_kernel(const float* __restrict__ D,
                                                      const float* __restrict__ proj,
                                                      float* __restrict__ out) {
    extern __shared__ float smem[];
    const int t  = threadIdx.x;
    const int w  = t >> 5;
    const int l  = t & 31;
    const int i0 = blockIdx.x * TM;

    float* wbuf    = smem + w * (STAGES * 512);            // 4 stages x 2KB
    float* scratch = smem + NW * STAGES * 512 + w * 8;     // 8 scores per warp
    const uint32_t wbuf_s = (uint32_t)__cvta_generic_to_shared(wbuf);

    const float scale = 0.08838834764831845f;              // 1/sqrt(DK+DR)

    // Pre-scaled Q,R fragments for the tile's 8 rows (dims 2l,2l+1).
    float2 q2[TM], r2[TM];
#pragma unroll
    for (int i = 0; i < TM; i++) {
        const float* row = proj + (size_t)(i0 + i) * PROJC;
        float2 qq = *(const float2*)(row + 2 * l);
        float2 rr = *(const float2*)(row + 192 + 2 * l);
        q2[i] = make_float2(qq.x * scale, qq.y * scale);
        r2[i] = make_float2(rr.x * scale, rr.y * scale);
    }

    // Prologue: fill all 4 stages. Stage = 8 rows x 256B; lane l copies
    // 4 x 16B chunks: flat idx = l + 32c -> row = idx>>4, u = idx&15.
#pragma unroll
    for (int s = 0; s < STAGES; s++) {
        int j = w + NW * s;
#pragma unroll
        for (int c = 0; c < 4; c++) {
            int idx = l + 32 * c;
            const float* g = D + (((size_t)(i0 + (idx >> 4)) * N + j) << 6) + ((idx & 15) << 2);
            cp16(wbuf_s + (uint32_t)(s * 2048 + idx * 16), g);
        }
        asm volatile("cp.async.commit_group;\n" ::: "memory");
    }

    // Prefetch K/V for j = w.
    float2 kv = *(const float2*)(proj + (size_t)w * PROJC + 64 + 2 * l);
    float2 vv = *(const float2*)(proj + (size_t)w * PROJC + 128 + 2 * l);

    const int irow = ((l >> 4) & 1) | (((l >> 3) & 1) << 1) | (((l >> 2) & 1) << 2);

    float  sum[TM];
    float2 acc[TM];
#pragma unroll
    for (int i = 0; i < TM; i++) { sum[i] = 0.f; acc[i] = make_float2(0.f, 0.f); }

    for (int k = 0; k < NIT; k++) {
        asm volatile("cp.async.wait_group 3;\n" ::: "memory");
        __syncwarp();

        const float* Db = wbuf + (k & 3) * 512;
        float v[TM];
#pragma unroll
        for (int r = 0; r < TM; r++) {
            float2 dv = *(const float2*)(Db + r * 64 + 2 * l);
            v[r] = fmaf(dv.x, r2[r].x,
                   fmaf(dv.y, r2[r].y,
                   fmaf(kv.x, q2[r].x, kv.y * q2[r].y)));
        }
        float c0 = combine2(v[0], v[1], 16, l);
        float c1 = combine2(v[2], v[3], 16, l);
        float c2 = combine2(v[4], v[5], 16, l);
        float c3 = combine2(v[6], v[7], 16, l);
        float d0 = combine2(c0, c1, 8, l);
        float d1 = combine2(c2, c3, 8, l);
        float e0 = combine2(d0, d1, 4, l);
        float f  = e0 + __shfl_xor_sync(0xffffffffu, e0, 2);
        float g  = f + __shfl_xor_sync(0xffffffffu, f, 1);
        if ((l & 3) == 0) scratch[irow] = g;
        __syncwarp();

        // Refill the stage we just consumed (j = w + 8*(k+4)).
        if (k + STAGES < NIT) {
            int j = w + NW * (k + STAGES);
#pragma unroll
            for (int c = 0; c < 4; c++) {
                int idx = l + 32 * c;
                const float* gp = D + (((size_t)(i0 + (idx >> 4)) * N + j) << 6) + ((idx & 15) << 2);
                cp16(wbuf_s + (uint32_t)((k & 3) * 2048 + idx * 16), gp);
            }
        }
        asm volatile("cp.async.commit_group;\n" ::: "memory");

        // Scores (replicated across lanes) + prefetch next K/V.
        float4 s0 = *(const float4*)scratch;
        float4 s1 = *(const float4*)(scratch + 4);
        int jn = (w + NW * (k + 1)) & (N - 1);
        float2 kn = *(const float2*)(proj + (size_t)jn * PROJC + 64 + 2 * l);
        float2 vn = *(const float2*)(proj + (size_t)jn * PROJC + 128 + 2 * l);

        float p;
        p = __expf(s0.x); sum[0] += p; acc[0].x = fmaf(p, vv.x, acc[0].x); acc[0].y = fmaf(p, vv.y, acc[0].y);
        p = __expf(s0.y); sum[1] += p; acc[1].x = fmaf(p, vv.x, acc[1].x); acc[1].y = fmaf(p, vv.y, acc[1].y);
        p = __expf(s0.z); sum[2] += p; acc[2].x = fmaf(p, vv.x, acc[2].x); acc[2].y = fmaf(p, vv.y, acc[2].y);
        p = __expf(s0.w); sum[3] += p; acc[3].x = fmaf(p, vv.x, acc[3].x); acc[3].y = fmaf(p, vv.y, acc[3].y);
        p = __expf(s1.x); sum[4] += p; acc[4].x = fmaf(p, vv.x, acc[4].x); acc[4].y = fmaf(p, vv.y, acc[4].y);
        p = __expf(s1.y); sum[5] += p; acc[5].x = fmaf(p, vv.x, acc[5].x); acc[5].y = fmaf(p, vv.y, acc[5].y);
        p = __expf(s1.z); sum[6] += p; acc[6].x = fmaf(p, vv.x, acc[6].x); acc[6].y = fmaf(p, vv.y, acc[6].y);
        p = __expf(s1.w); sum[7] += p; acc[7].x = fmaf(p, vv.x, acc[7].x); acc[7].y = fmaf(p, vv.y, acc[7].y);

        kv = kn; vv = vn;
    }

    asm volatile("cp.async.wait_group 0;\n" ::: "memory");

    // ---------------- epilogue: combine the 8 warps' partials ----------------
    __syncthreads();
    float* accsh = smem;                   // [8][8][64]
    float* sumsh = smem + NW * TM * 64;    // [8][8]
#pragma unroll
    for (int r = 0; r < TM; r++)
        *(float2*)(accsh + ((w * TM + r) * 64) + 2 * l) = acc[r];
    if (l == 0) {
#pragma unroll
        for (int r = 0; r < TM; r++) sumsh[w * TM + r] = sum[r];
    }
    __syncthreads();
    {
        float2 tot = make_float2(0.f, 0.f);
        float  st  = 0.f;
#pragma unroll
        for (int ww = 0; ww < NW; ww++) {
            float2 a = *(const float2*)(accsh + ((ww * TM + w) * 64) + 2 * l);
            tot.x += a.x; tot.y += a.y;
            st += sumsh[ww * TM + w];
        }
        float inv = 1.0f / st;
        *(float2*)(out + (size_t)(i0 + w) * 64 + 2 * l) = make_float2(tot.x * inv, tot.y * inv);
    }
}

// ---------------------------------------------------------------------------
extern "C" void kernel_launch(void* const* d_in, const int* in_sizes, int n_in,
                              void* d_out, int out_size) {
    const float* H = (const float*)d_in[0];
    const float* D = (const float*)d_in[1];
    const float* W = (const float*)d_in[2];
    float* out = (float*)d_out;

    const int attn_smem = (NW * STAGES * 512 + NW * 8) * 4;           // 65,792 B
    cudaFuncSetAttribute(attn_kernel, cudaFuncAttributeMaxDynamicSharedMemorySize, attn_smem);

    void* proj_ptr = nullptr;
    cudaGetSymbolAddress(&proj_ptr, g_proj);
    float* proj = (float*)proj_ptr;

    dim3 pgrid(N / BM, PROJC / BN);
    proj_kernel<<<pgrid, 256>>>(H, W, proj);
    attn_kernel<<<N / TM, 256, attn_smem>>>(D, proj, out);
}

// round 10
// speedup vs baseline: 1.4288x; 1.0128x over previous
#include <cuda_runtime.h>
#include <cstdint>

#define N      2048
#define DIN    256
#define PROJC  256
#define TM     8           // attn rows per CTA
#define NW     8           // warps per attn CTA
#define STAGES 4
#define NIT    (N / NW)    // 256 j-iterations per warp, j = w + 8k

// proj GEMM tiles
#define BM 64
#define BN 64
#define BK 32

// 2 MB scratch for projection output: cols = [Q(64) | K(64) | V(64) | R(64)]
__device__ float g_proj[N * PROJC];

// ---------------------------------------------------------------------------
// Kernel 1: proj = H @ W^T  — tiled GEMM, 64x64 tile, 4x4 micro-tile/thread.
// ---------------------------------------------------------------------------
__global__ __launch_bounds__(256) void proj_kernel(const float* __restrict__ H,
                                                   const float* __restrict__ W,
                                                   float* __restrict__ proj) {
    __shared__ float Hs[BK][BM + 4];
    __shared__ float Ws[BK][BN + 4];

    const int t  = threadIdx.x;
    const int tx = t & 15;
    const int ty = t >> 4;
    const int m0 = blockIdx.x * BM;
    const int n0 = blockIdx.y * BN;

    float acc[4][4];
#pragma unroll
    for (int i = 0; i < 4; i++)
#pragma unroll
        for (int j = 0; j < 4; j++) acc[i][j] = 0.f;

    for (int kc = 0; kc < DIN; kc += BK) {
#pragma unroll
        for (int q = 0; q < 2; q++) {
            int idx = t + q * 256;
            int row = idx >> 3;
            int k4  = idx & 7;
            float4 hv = *(const float4*)(H + (size_t)(m0 + row) * DIN + kc + k4 * 4);
            Hs[k4 * 4 + 0][row] = hv.x;
            Hs[k4 * 4 + 1][row] = hv.y;
            Hs[k4 * 4 + 2][row] = hv.z;
            Hs[k4 * 4 + 3][row] = hv.w;
            float4 wv = *(const float4*)(W + (size_t)(n0 + row) * DIN + kc + k4 * 4);
            Ws[k4 * 4 + 0][row] = wv.x;
            Ws[k4 * 4 + 1][row] = wv.y;
            Ws[k4 * 4 + 2][row] = wv.z;
            Ws[k4 * 4 + 3][row] = wv.w;
        }
        __syncthreads();
#pragma unroll
        for (int k = 0; k < BK; k++) {
            float4 a = *(const float4*)&Hs[k][ty * 4];
            float4 b = *(const float4*)&Ws[k][tx * 4];
            acc[0][0] = fmaf(a.x, b.x, acc[0][0]); acc[0][1] = fmaf(a.x, b.y, acc[0][1]);
            acc[0][2] = fmaf(a.x, b.z, acc[0][2]); acc[0][3] = fmaf(a.x, b.w, acc[0][3]);
            acc[1][0] = fmaf(a.y, b.x, acc[1][0]); acc[1][1] = fmaf(a.y, b.y, acc[1][1]);
            acc[1][2] = fmaf(a.y, b.z, acc[1][2]); acc[1][3] = fmaf(a.y, b.w, acc[1][3]);
            acc[2][0] = fmaf(a.z, b.x, acc[2][0]); acc[2][1] = fmaf(a.z, b.y, acc[2][1]);
            acc[2][2] = fmaf(a.z, b.z, acc[2][2]); acc[2][3] = fmaf(a.z, b.w, acc[2][3]);
            acc[3][0] = fmaf(a.w, b.x, acc[3][0]); acc[3][1] = fmaf(a.w, b.y, acc[3][1]);
            acc[3][2] = fmaf(a.w, b.z, acc[3][2]); acc[3][3] = fmaf(a.w, b.w, acc[3][3]);
        }
        __syncthreads();
    }
#pragma unroll
    for (int i = 0; i < 4; i++) {
        float4 o = make_float4(acc[i][0], acc[i][1], acc[i][2], acc[i][3]);
        *(float4*)(proj + (size_t)(m0 + ty * 4 + i) * PROJC + n0 + tx * 4) = o;
    }
}

// ---------------------------------------------------------------------------
__device__ __forceinline__ float combine2(float a, float b, int mask, int l) {
    float sel = (l & mask) ? a : b;
    float t = __shfl_xor_sync(0xffffffffu, sel, mask);
    return (l & mask) ? (b + t) : (a + t);
}

__device__ __forceinline__ void cp16(uint32_t s, const void* g) {
    asm volatile("cp.async.cg.shared.global [%0], [%1], 16;\n" :: "r"(s), "l"(g));
}

// ---------------------------------------------------------------------------
// Kernel 2: fused scores + max-free online softmax + P@V.
// R4 datapath, but TWO j-iterations between each pipeline barrier:
// stages are filled/awaited in groups of two (wait_group 1 => 8 KB/warp in
// flight), and the two independent shfl reduction trees overlap.
// ---------------------------------------------------------------------------
__global__ __launch_bounds__(256, 2) void attn_kernel(const float* __restrict__ D,
                                                      const float* __restrict__ proj,
                                                      float* __restrict__ out) {
    extern __shared__ float smem[];
    const int t  = threadIdx.x;
    const int w  = t >> 5;
    const int l  = t & 31;
    const int i0 = blockIdx.x * TM;

    float* wbuf    = smem + w * (STAGES * 512);            // 4 stages x 2KB
    float* scratch = smem + NW * STAGES * 512 + w * 16;    // 16 scores per warp
    const uint32_t wbuf_s = (uint32_t)__cvta_generic_to_shared(wbuf);

    const float scale = 0.08838834764831845f;              // 1/sqrt(DK+DR)

    // Pre-scaled Q,R fragments for the tile's 8 rows (dims 2l,2l+1).
    float2 q2[TM], r2[TM];
#pragma unroll
    for (int i = 0; i < TM; i++) {
        const float* row = proj + (size_t)(i0 + i) * PROJC;
        float2 qq = *(const float2*)(row + 2 * l);
        float2 rr = *(const float2*)(row + 192 + 2 * l);
        q2[i] = make_float2(qq.x * scale, qq.y * scale);
        r2[i] = make_float2(rr.x * scale, rr.y * scale);
    }

    // Prologue: fill 4 stages as TWO commit groups of two stages each.
#pragma unroll
    for (int gq = 0; gq < 2; gq++) {
#pragma unroll
        for (int sq = 0; sq < 2; sq++) {
            int s = gq * 2 + sq;
            int j = w + NW * s;
#pragma unroll
            for (int c = 0; c < 4; c++) {
                int idx = l + 32 * c;
                const float* g = D + (((size_t)(i0 + (idx >> 4)) * N + j) << 6) + ((idx & 15) << 2);
                cp16(wbuf_s + (uint32_t)(s * 2048 + idx * 16), g);
            }
        }
        asm volatile("cp.async.commit_group;\n" ::: "memory");
    }

    // Prefetch K/V for j = w and j = w+8.
    float2 kv0 = *(const float2*)(proj + (size_t)w * PROJC + 64 + 2 * l);
    float2 vv0 = *(const float2*)(proj + (size_t)w * PROJC + 128 + 2 * l);
    float2 kv1 = *(const float2*)(proj + (size_t)(w + NW) * PROJC + 64 + 2 * l);
    float2 vv1 = *(const float2*)(proj + (size_t)(w + NW) * PROJC + 128 + 2 * l);

    const int irow = ((l >> 4) & 1) | (((l >> 3) & 1) << 1) | (((l >> 2) & 1) << 2);

    float  sum[TM];
    float2 acc[TM];
#pragma unroll
    for (int i = 0; i < TM; i++) { sum[i] = 0.f; acc[i] = make_float2(0.f, 0.f); }

    for (int kk = 0; kk < NIT / 2; kk++) {
        const int k0 = 2 * kk, k1 = 2 * kk + 1;
        asm volatile("cp.async.wait_group 1;\n" ::: "memory");
        __syncwarp();

        // -------- sub-iteration A (stage k0&3, j = w+8*k0) --------
        const float* Da = wbuf + (k0 & 3) * 512;
        float va[TM];
#pragma unroll
        for (int r = 0; r < TM; r++) {
            float2 dv = *(const float2*)(Da + r * 64 + 2 * l);
            va[r] = fmaf(dv.x, r2[r].x,
                    fmaf(dv.y, r2[r].y,
                    fmaf(kv0.x, q2[r].x, kv0.y * q2[r].y)));
        }
        // -------- sub-iteration B (stage k1&3, j = w+8*k1) --------
        const float* Dbp = wbuf + (k1 & 3) * 512;
        float vb[TM];
#pragma unroll
        for (int r = 0; r < TM; r++) {
            float2 dv = *(const float2*)(Dbp + r * 64 + 2 * l);
            vb[r] = fmaf(dv.x, r2[r].x,
                    fmaf(dv.y, r2[r].y,
                    fmaf(kv1.x, q2[r].x, kv1.y * q2[r].y)));
        }

        // Two independent packed reduction trees (ptxas interleaves them).
        float ac0 = combine2(va[0], va[1], 16, l);
        float bc0 = combine2(vb[0], vb[1], 16, l);
        float ac1 = combine2(va[2], va[3], 16, l);
        float bc1 = combine2(vb[2], vb[3], 16, l);
        float ac2 = combine2(va[4], va[5], 16, l);
        float bc2 = combine2(vb[4], vb[5], 16, l);
        float ac3 = combine2(va[6], va[7], 16, l);
        float bc3 = combine2(vb[6], vb[7], 16, l);
        float ad0 = combine2(ac0, ac1, 8, l);
        float bd0 = combine2(bc0, bc1, 8, l);
        float ad1 = combine2(ac2, ac3, 8, l);
        float bd1 = combine2(bc2, bc3, 8, l);
        float ae0 = combine2(ad0, ad1, 4, l);
        float be0 = combine2(bd0, bd1, 4, l);
        float af  = ae0 + __shfl_xor_sync(0xffffffffu, ae0, 2);
        float bf  = be0 + __shfl_xor_sync(0xffffffffu, be0, 2);
        float ag  = af + __shfl_xor_sync(0xffffffffu, af, 1);
        float bg  = bf + __shfl_xor_sync(0xffffffffu, bf, 1);
        if ((l & 3) == 0) {
            scratch[irow]     = ag;
            scratch[8 + irow] = bg;
        }
        __syncwarp();

        // Refill both consumed stages (j = w+8*(k+4)) as ONE commit group.
        if (k0 + STAGES < NIT) {
            int j = w + NW * (k0 + STAGES);
#pragma unroll
            for (int c = 0; c < 4; c++) {
                int idx = l + 32 * c;
                const float* gp = D + (((size_t)(i0 + (idx >> 4)) * N + j) << 6) + ((idx & 15) << 2);
                cp16(wbuf_s + (uint32_t)((k0 & 3) * 2048 + idx * 16), gp);
            }
        }
        if (k1 + STAGES < NIT) {
            int j = w + NW * (k1 + STAGES);
#pragma unroll
            for (int c = 0; c < 4; c++) {
                int idx = l + 32 * c;
                const float* gp = D + (((size_t)(i0 + (idx >> 4)) * N + j) << 6) + ((idx & 15) << 2);
                cp16(wbuf_s + (uint32_t)((k1 & 3) * 2048 + idx * 16), gp);
            }
        }
        asm volatile("cp.async.commit_group;\n" ::: "memory");

        // Scores for both sub-iterations + prefetch next two K/V pairs.
        float4 a0 = *(const float4*)scratch;
        float4 a1 = *(const float4*)(scratch + 4);
        float4 b0 = *(const float4*)(scratch + 8);
        float4 b1 = *(const float4*)(scratch + 12);
        int jn0 = (w + NW * (k0 + 2)) & (N - 1);
        int jn1 = (w + NW * (k1 + 2)) & (N - 1);
        float2 kn0 = *(const float2*)(proj + (size_t)jn0 * PROJC + 64 + 2 * l);
        float2 vn0 = *(const float2*)(proj + (size_t)jn0 * PROJC + 128 + 2 * l);
        float2 kn1 = *(const float2*)(proj + (size_t)jn1 * PROJC + 64 + 2 * l);
        float2 vn1 = *(const float2*)(proj + (size_t)jn1 * PROJC + 128 + 2 * l);

        float p;
        p = __expf(a0.x); sum[0] += p; acc[0].x = fmaf(p, vv0.x, acc[0].x); acc[0].y = fmaf(p, vv0.y, acc[0].y);
        p = __expf(a0.y); sum[1] += p; acc[1].x = fmaf(p, vv0.x, acc[1].x); acc[1].y = fmaf(p, vv0.y, acc[1].y);
        p = __expf(a0.z); sum[2] += p; acc[2].x = fmaf(p, vv0.x, acc[2].x); acc[2].y = fmaf(p, vv0.y, acc[2].y);
        p = __expf(a0.w); sum[3] += p; acc[3].x = fmaf(p, vv0.x, acc[3].x); acc[3].y = fmaf(p, vv0.y, acc[3].y);
        p = __expf(a1.x); sum[4] += p; acc[4].x = fmaf(p, vv0.x, acc[4].x); acc[4].y = fmaf(p, vv0.y, acc[4].y);
        p = __expf(a1.y); sum[5] += p; acc[5].x = fmaf(p, vv0.x, acc[5].x); acc[5].y = fmaf(p, vv0.y, acc[5].y);
        p = __expf(a1.z); sum[6] += p; acc[6].x = fmaf(p, vv0.x, acc[6].x); acc[6].y = fmaf(p, vv0.y, acc[6].y);
        p = __expf(a1.w); sum[7] += p; acc[7].x = fmaf(p, vv0.x, acc[7].x); acc[7].y = fmaf(p, vv0.y, acc[7].y);

        p = __expf(b0.x); sum[0] += p; acc[0].x = fmaf(p, vv1.x, acc[0].x); acc[0].y = fmaf(p, vv1.y, acc[0].y);
        p = __expf(b0.y); sum[1] += p; acc[1].x = fmaf(p, vv1.x, acc[1].x); acc[1].y = fmaf(p, vv1.y, acc[1].y);
        p = __expf(b0.z); sum[2] += p; acc[2].x = fmaf(p, vv1.x, acc[2].x); acc[2].y = fmaf(p, vv1.y, acc[2].y);
        p = __expf(b0.w); sum[3] += p; acc[3].x = fmaf(p, vv1.x, acc[3].x); acc[3].y = fmaf(p, vv1.y, acc[3].y);
        p = __expf(b1.x); sum[4] += p; acc[4].x = fmaf(p, vv1.x, acc[4].x); acc[4].y = fmaf(p, vv1.y, acc[4].y);
        p = __expf(b1.y); sum[5] += p; acc[5].x = fmaf(p, vv1.x, acc[5].x); acc[5].y = fmaf(p, vv1.y, acc[5].y);
        p = __expf(b1.z); sum[6] += p; acc[6].x = fmaf(p, vv1.x, acc[6].x); acc[6].y = fmaf(p, vv1.y, acc[6].y);
        p = __expf(b1.w); sum[7] += p; acc[7].x = fmaf(p, vv1.x, acc[7].x); acc[7].y = fmaf(p, vv1.y, acc[7].y);

        kv0 = kn0; vv0 = vn0;
        kv1 = kn1; vv1 = vn1;
    }

    asm volatile("cp.async.wait_group 0;\n" ::: "memory");

    // ---------------- epilogue: combine the 8 warps' partials ----------------
    __syncthreads();
    float* accsh = smem;                   // [8][8][64]
    float* sumsh = smem + NW * TM * 64;    // [8][8]
#pragma unroll
    for (int r = 0; r < TM; r++)
        *(float2*)(accsh + ((w * TM + r) * 64) + 2 * l) = acc[r];
    if (l == 0) {
#pragma unroll
        for (int r = 0; r < TM; r++) sumsh[w * TM + r] = sum[r];
    }
    __syncthreads();
    {
        float2 tot = make_float2(0.f, 0.f);
        float  st  = 0.f;
#pragma unroll
        for (int ww = 0; ww < NW; ww++) {
            float2 a = *(const float2*)(accsh + ((ww * TM + w) * 64) + 2 * l);
            tot.x += a.x; tot.y += a.y;
            st += sumsh[ww * TM + w];
        }
        float inv = 1.0f / st;
        *(float2*)(out + (size_t)(i0 + w) * 64 + 2 * l) = make_float2(tot.x * inv, tot.y * inv);
    }
}

// ---------------------------------------------------------------------------
extern "C" void kernel_launch(void* const* d_in, const int* in_sizes, int n_in,
                              void* d_out, int out_size) {
    const float* H = (const float*)d_in[0];
    const float* D = (const float*)d_in[1];
    const float* W = (const float*)d_in[2];
    float* out = (float*)d_out;

    const int attn_smem = (NW * STAGES * 512 + NW * 16) * 4;          // 66,048 B
    cudaFuncSetAttribute(attn_kernel, cudaFuncAttributeMaxDynamicSharedMemorySize, attn_smem);

    void* proj_ptr = nullptr;
    cudaGetSymbolAddress(&proj_ptr, g_proj);
    float* proj = (float*)proj_ptr;

    dim3 pgrid(N / BM, PROJC / BN);
    proj_kernel<<<pgrid, 256>>>(H, W, proj);
    attn_kernel<<<N / TM, 256, attn_smem>>>(D, proj, out);
}